// round 7
// baseline (speedup 1.0000x reference)
#include <cuda_runtime.h>

#define NEU   64
#define HID   32
#define GD    103
#define N_MAX 2000128
#define B_MAX 8192

typedef unsigned long long ull;

// Scratch (no allocations allowed in kernel_launch)
__device__ float        g_logit[N_MAX];
__device__ float        g_G[B_MAX * HID];
__device__ unsigned int g_maxenc[B_MAX];
__device__ float        g_sum[B_MAX];

// Monotonic float <-> uint encoding for atomicMax on floats
__device__ __forceinline__ unsigned int enc_f(float f) {
    unsigned int u = __float_as_uint(f);
    return (u & 0x80000000u) ? ~u : (u | 0x80000000u);
}
__device__ __forceinline__ float dec_f(unsigned int u) {
    u = (u & 0x80000000u) ? (u & 0x7FFFFFFFu) : ~u;
    return __uint_as_float(u);
}

// Packed f32x2 helpers
__device__ __forceinline__ ull fma2(ull a, ull b, ull c) {
    ull d;
    asm("fma.rn.f32x2 %0, %1, %2, %3;" : "=l"(d) : "l"(a), "l"(b), "l"(c));
    return d;
}
__device__ __forceinline__ ull pack2(float lo, float hi) {
    ull d;
    asm("mov.b64 %0, {%1, %2};" : "=l"(d) : "f"(lo), "f"(hi));
    return d;
}
__device__ __forceinline__ void unpack2(ull v, float& lo, float& hi) {
    asm("mov.b64 {%0, %1}, %2;" : "=f"(lo), "=f"(hi) : "l"(v));
}

// ---------------------------------------------------------------------------
__global__ void k_init(int b) {
    int i = blockIdx.x * blockDim.x + threadIdx.x;
    if (i < b) {
        g_maxenc[i] = 0u;
        g_sum[i]    = 0.0f;
    }
}

// ---------------------------------------------------------------------------
__global__ void k_graph(const float* __restrict__ gf,
                        const float* __restrict__ W1,
                        const float* __restrict__ b1, int b) {
    int warp = (blockIdx.x * blockDim.x + threadIdx.x) >> 5;
    int lane = threadIdx.x & 31;
    if (warp >= b) return;

    const float* row = gf + (size_t)warp * GD;
    float r0 = row[lane];
    float r1 = row[32 + lane];
    float r2 = row[64 + lane];
    float r3 = (lane < (GD - 96)) ? row[96 + lane] : 0.0f;

    float acc = b1[lane];
#pragma unroll
    for (int d = 0; d < GD; d++) {
        float v;
        if      (d < 32) v = __shfl_sync(0xFFFFFFFFu, r0, d);
        else if (d < 64) v = __shfl_sync(0xFFFFFFFFu, r1, d - 32);
        else if (d < 96) v = __shfl_sync(0xFFFFFFFFu, r2, d - 64);
        else             v = __shfl_sync(0xFFFFFFFFu, r3, d - 96);
        acc = fmaf(v, W1[(NEU + d) * HID + lane], acc);
    }
    g_G[warp * HID + lane] = acc;
}

// ---------------------------------------------------------------------------
// k_logits v5: coalesced staging, split-H (4 threads/node), low footprint.
//   block = 128 threads, tile = 32 nodes (8.7 KB, padded rows of 34 ull)
//   thread (node_l = tid>>2, hq = tid&3) owns h-slice [8*hq, 8*hq+8)
//   acc[8] packed f32x2 over (even k, odd k)
//   sW1p layout [hq][k2][8] (stride 260 ull per hq -> banks 0/8/16/24)
// ---------------------------------------------------------------------------
#define TPB      128
#define XSTRIDE  34                       // ull per node row (pad)
#define WSTRIDE  260                      // ull per hq slab (32*8 + 4 pad)

__global__ void __launch_bounds__(TPB)
k_logits(const float* __restrict__ x,
         const int* __restrict__ nb,
         const float* __restrict__ W1,
         const float* __restrict__ W2,
         const float* __restrict__ b2, int n) {
    __shared__ ull   sW1p[4 * WSTRIDE];   // 8320 B
    __shared__ ull   tile[32 * XSTRIDE];  // 8704 B
    __shared__ float sW2[HID];
    __shared__ float sb2s[1];

    for (int t = threadIdx.x; t < (NEU / 2) * HID; t += TPB) {
        int k2 = t >> 5, h = t & 31;
        int hq = h >> 3, j = h & 7;
        sW1p[hq * WSTRIDE + k2 * 8 + j] =
            pack2(W1[(2 * k2) * HID + h], W1[(2 * k2 + 1) * HID + h]);
    }
    if (threadIdx.x < HID) sW2[threadIdx.x] = W2[threadIdx.x];
    if (threadIdx.x == 0)  sb2s[0] = b2[0];
    __syncthreads();
    float sb2 = sb2s[0];

    int tid    = threadIdx.x;
    int lane   = tid & 31;
    int node_l = tid >> 2;      // 0..31
    int hq     = tid & 3;       // h-slice

    int ntiles = (n + 31) / 32;

    for (int t = blockIdx.x; t < ntiles; t += gridDim.x) {
        long node0 = (long)t * 32;

        // ---- stage: 512 float4 chunks, fully coalesced ----
#pragma unroll
        for (int r = 0; r < 4; r++) {
            int  idx = r * TPB + tid;           // 0..511
            int  row = idx >> 4, m = idx & 15;
            long gn  = node0 + row;
            if (gn > n - 1) gn = n - 1;         // clamp (duplicate read, safe)
            float4 v = *(const float4*)(x + gn * NEU + m * 4);
            tile[row * XSTRIDE + 2 * m]     = pack2(v.x, v.y);
            tile[row * XSTRIDE + 2 * m + 1] = pack2(v.z, v.w);
        }
        __syncthreads();

        // ---- compute ----
        long gi    = node0 + node_l;
        bool valid = (gi < n);
        int  seg   = valid ? nb[gi] : -1;

        ull acc[8];
        {
            const float4* Gp = (const float4*)(g_G + (valid ? seg : 0) * HID + hq * 8);
            float4 a0 = Gp[0], a1 = Gp[1];
            acc[0] = pack2(a0.x, 0.f); acc[1] = pack2(a0.y, 0.f);
            acc[2] = pack2(a0.z, 0.f); acc[3] = pack2(a0.w, 0.f);
            acc[4] = pack2(a1.x, 0.f); acc[5] = pack2(a1.y, 0.f);
            acc[6] = pack2(a1.z, 0.f); acc[7] = pack2(a1.w, 0.f);
        }

        const ull* xr = tile + node_l * XSTRIDE;
        const ull* wb = sW1p + hq * WSTRIDE;
#pragma unroll 8
        for (int k2 = 0; k2 < 32; k2++) {
            ull xq = xr[k2];                                  // (x_{2k2}, x_{2k2+1})
            const ulonglong2* wr = (const ulonglong2*)(wb + k2 * 8);
            ulonglong2 w0 = wr[0], w1 = wr[1], w2 = wr[2], w3 = wr[3];
            acc[0] = fma2(xq, w0.x, acc[0]); acc[1] = fma2(xq, w0.y, acc[1]);
            acc[2] = fma2(xq, w1.x, acc[2]); acc[3] = fma2(xq, w1.y, acc[3]);
            acc[4] = fma2(xq, w2.x, acc[4]); acc[5] = fma2(xq, w2.y, acc[5]);
            acc[6] = fma2(xq, w3.x, acc[6]); acc[7] = fma2(xq, w3.y, acc[7]);
        }

        // ---- tail: softplus + partial dot(W2) over this h-slice ----
        float part = 0.0f;
#pragma unroll
        for (int j = 0; j < 8; j++) {
            float lo, hi;
            unpack2(acc[j], lo, hi);
            float a  = lo + hi;
            float sp = (a > 20.0f) ? a : __logf(1.0f + __expf(a));
            part = fmaf(sp, sW2[hq * 8 + j], part);
        }
        // reduce the 4 h-slices of this node
        part += __shfl_down_sync(0xFFFFFFFFu, part, 2);
        part += __shfl_down_sync(0xFFFFFFFFu, part, 1);
        float logit  = part + sb2;
        bool  holder = (hq == 0) && valid;
        if (holder) g_logit[gi] = logit;

        // segmented max among the 8 node-holders of this warp (stride 4)
        float v = holder ? logit : -3.4e38f;
#pragma unroll
        for (int off = 4; off < 32; off <<= 1) {
            int   oseg = __shfl_down_sync(0xFFFFFFFFu, seg, off);
            float ov   = __shfl_down_sync(0xFFFFFFFFu, v,   off);
            if (lane + off < 32 && oseg == seg) v = fmaxf(v, ov);
        }
        int  pseg = __shfl_up_sync(0xFFFFFFFFu, seg, 4);
        bool head = holder && (lane < 4 || pseg != seg);
        if (head && seg >= 0) atomicMax(&g_maxenc[seg], enc_f(v));

        __syncthreads();   // tile reuse
    }
}

// ---------------------------------------------------------------------------
__global__ void __launch_bounds__(256)
k_exp(const int* __restrict__ nb, int n) {
    int i = blockIdx.x * blockDim.x + threadIdx.x;
    int lane = threadIdx.x & 31;

    int   seg = -1;
    float e   = 0.0f;
    if (i < n) {
        seg = nb[i];
        float mx = dec_f(g_maxenc[seg]);
        e = __expf(g_logit[i] - mx);
    }

#pragma unroll
    for (int off = 1; off < 32; off <<= 1) {
        int   oseg = __shfl_down_sync(0xFFFFFFFFu, seg, off);
        float oe   = __shfl_down_sync(0xFFFFFFFFu, e,   off);
        if (lane + off < 32 && oseg == seg) e += oe;
    }
    int  pseg = __shfl_up_sync(0xFFFFFFFFu, seg, 1);
    bool head = (lane == 0) || (pseg != seg);
    if (head && seg >= 0) atomicAdd(&g_sum[seg], e);
}

// ---------------------------------------------------------------------------
__global__ void __launch_bounds__(256)
k_div(const int* __restrict__ nb, float* __restrict__ out, int n) {
    int i = blockIdx.x * blockDim.x + threadIdx.x;
    if (i < n) {
        int   seg = nb[i];
        float mx  = dec_f(g_maxenc[seg]);
        float e   = __expf(g_logit[i] - mx);
        out[i] = e / g_sum[seg];
    }
}

// ---------------------------------------------------------------------------
extern "C" void kernel_launch(void* const* d_in, const int* in_sizes, int n_in,
                              void* d_out, int out_size) {
    const float* x   = (const float*)d_in[0];
    const int*   nb  = (const int*)d_in[1];
    const float* gf  = (const float*)d_in[2];
    const float* W1  = (const float*)d_in[3];
    const float* b1  = (const float*)d_in[4];
    const float* W2  = (const float*)d_in[5];
    const float* b2  = (const float*)d_in[6];
    float*       out = (float*)d_out;

    int n = in_sizes[0] / NEU;   // nodes
    int b = in_sizes[2] / GD;    // graphs

    k_init<<<(b + 255) / 256, 256>>>(b);
    k_graph<<<(b + 7) / 8, 256>>>(gf, W1, b1, b);

    k_logits<<<1480, TPB>>>(x, nb, W1, W2, b2, n);

    int blocks = (n + 255) / 256;
    k_exp<<<blocks, 256>>>(nb, n);
    k_div<<<blocks, 256>>>(nb, out, n);
}

// round 9
// speedup vs baseline: 2.1964x; 2.1964x over previous
#include <cuda_runtime.h>
#include <cuda_bf16.h>
#include <cstdint>

#define NEU   64
#define HID   32
#define GD    103
#define N_MAX 2000128
#define B_MAX 8192

typedef unsigned long long ull;

// Scratch
__device__ float        g_logit[N_MAX];
__device__ float        g_G[B_MAX * HID];
__device__ unsigned int g_maxenc[B_MAX];
__device__ float        g_sum[B_MAX];

__device__ __forceinline__ unsigned int enc_f(float f) {
    unsigned int u = __float_as_uint(f);
    return (u & 0x80000000u) ? ~u : (u | 0x80000000u);
}
__device__ __forceinline__ float dec_f(unsigned int u) {
    u = (u & 0x80000000u) ? (u & 0x7FFFFFFFu) : ~u;
    return __uint_as_float(u);
}

__device__ __forceinline__ uint32_t smem_u32(const void* p) {
    uint32_t a;
    asm("{ .reg .u64 t; cvta.to.shared.u64 t, %1; cvt.u32.u64 %0, t; }"
        : "=r"(a) : "l"(p));
    return a;
}
__device__ __forceinline__ void ldsm_x4(uint32_t r[4], uint32_t addr) {
    asm volatile("ldmatrix.sync.aligned.m8n8.x4.shared.b16 {%0,%1,%2,%3}, [%4];"
        : "=r"(r[0]), "=r"(r[1]), "=r"(r[2]), "=r"(r[3]) : "r"(addr));
}
__device__ __forceinline__ void ldsm_x2(uint32_t r[2], uint32_t addr) {
    asm volatile("ldmatrix.sync.aligned.m8n8.x2.shared.b16 {%0,%1}, [%2];"
        : "=r"(r[0]), "=r"(r[1]) : "r"(addr));
}
__device__ __forceinline__ void mma_bf16(float c[4], const uint32_t a[4],
                                         const uint32_t b[2]) {
    asm volatile(
        "mma.sync.aligned.m16n8k16.row.col.f32.bf16.bf16.f32 "
        "{%0,%1,%2,%3}, {%4,%5,%6,%7}, {%8,%9}, {%0,%1,%2,%3};"
        : "+f"(c[0]), "+f"(c[1]), "+f"(c[2]), "+f"(c[3])
        : "r"(a[0]), "r"(a[1]), "r"(a[2]), "r"(a[3]), "r"(b[0]), "r"(b[1]));
}

// ---------------------------------------------------------------------------
__global__ void k_init(int b) {
    int i = blockIdx.x * blockDim.x + threadIdx.x;
    if (i < b) { g_maxenc[i] = 0u; g_sum[i] = 0.0f; }
}

// ---------------------------------------------------------------------------
__global__ void k_graph(const float* __restrict__ gf,
                        const float* __restrict__ W1,
                        const float* __restrict__ b1, int b) {
    int warp = (blockIdx.x * blockDim.x + threadIdx.x) >> 5;
    int lane = threadIdx.x & 31;
    if (warp >= b) return;

    const float* row = gf + (size_t)warp * GD;
    float r0 = row[lane];
    float r1 = row[32 + lane];
    float r2 = row[64 + lane];
    float r3 = (lane < (GD - 96)) ? row[96 + lane] : 0.0f;

    float acc = b1[lane];
#pragma unroll
    for (int d = 0; d < GD; d++) {
        float v;
        if      (d < 32) v = __shfl_sync(0xFFFFFFFFu, r0, d);
        else if (d < 64) v = __shfl_sync(0xFFFFFFFFu, r1, d - 32);
        else if (d < 96) v = __shfl_sync(0xFFFFFFFFu, r2, d - 64);
        else             v = __shfl_sync(0xFFFFFFFFu, r3, d - 96);
        acc = fmaf(v, W1[(NEU + d) * HID + lane], acc);
    }
    g_G[warp * HID + lane] = acc;
}

// ---------------------------------------------------------------------------
// k_logits v7 (mma.sync bf16-split HMMA):
//   D[128,32] = Ah Bh^T + Al Bh^T + Ah Bl^T  (fp32 accum)
//   A = x tile (bf16 hi/lo), rows padded to 144 B for conflict-free ldmatrix
//   B = W1[0:64]^T as [h][k] hi/lo tiles; fragments persisted in registers
// ---------------------------------------------------------------------------
#define STRB   144                       // bytes per smem row (64 bf16 + pad)
#define OFF_AH 0
#define OFF_AL 18432                     // 128*144
#define OFF_WH 36864
#define OFF_WL 41472                     // + 32*144
#define OFF_W2 46080
#define OFF_B2 46208
#define SMEMSZ 46336

__global__ void __launch_bounds__(128)
k_logits(const float* __restrict__ x,
         const int* __restrict__ nb,
         const float* __restrict__ W1,
         const float* __restrict__ W2,
         const float* __restrict__ b2, int n) {
    __shared__ __align__(128) char s[SMEMSZ];
    uint32_t sb  = smem_u32(s);
    int tid  = threadIdx.x;
    int w    = tid >> 5;
    int l    = tid & 31;

    // ---- W1[0:64] -> Wh/Wl [h][k] bf16 tiles (transpose) ----
    for (int t = tid; t < NEU * HID; t += 128) {
        int k = t >> 5, h = t & 31;          // W1[k][h] = W1[t]
        float wv = W1[t];
        __nv_bfloat16 wh = __float2bfloat16(wv);
        float wl = wv - __bfloat162float(wh);
        ((__nv_bfloat16*)(s + OFF_WH))[h * 72 + k] = wh;
        ((__nv_bfloat16*)(s + OFF_WL))[h * 72 + k] = __float2bfloat16(wl);
    }
    if (tid < HID) ((float*)(s + OFF_W2))[tid] = W2[tid];
    if (tid == 0)  ((float*)(s + OFF_B2))[0]   = b2[0];

    // ---- x tile: warp stages its own 32 nodes, coalesced ----
    long node0 = (long)blockIdx.x * 128;
    {
        int m = l & 15, half = l >> 4;
#pragma unroll
        for (int j = 0; j < 16; j++) {
            int  nl = w * 32 + 2 * j + half;
            long gn = node0 + nl;
            if (gn > n - 1) gn = n - 1;
            float4 v = *(const float4*)(x + gn * NEU + m * 4);
            __nv_bfloat162 h0 = __floats2bfloat162_rn(v.x, v.y);
            __nv_bfloat162 h1 = __floats2bfloat162_rn(v.z, v.w);
            __nv_bfloat162 l0 = __floats2bfloat162_rn(v.x - __bfloat162float(h0.x),
                                                      v.y - __bfloat162float(h0.y));
            __nv_bfloat162 l1 = __floats2bfloat162_rn(v.z - __bfloat162float(h1.x),
                                                      v.w - __bfloat162float(h1.y));
            union { __nv_bfloat162 p[2]; ull u; } ph, pl;
            ph.p[0] = h0; ph.p[1] = h1;
            pl.p[0] = l0; pl.p[1] = l1;
            *(ull*)(s + OFF_AH + nl * STRB + m * 8) = ph.u;
            *(ull*)(s + OFF_AL + nl * STRB + m * 8) = pl.u;
        }
    }
    __syncthreads();

    int g = l >> 2, t4 = l & 3;

    // persist W2 pairs for this lane's h columns
    float2 w2p[4];
#pragma unroll
    for (int n8 = 0; n8 < 4; n8++)
        w2p[n8] = *(const float2*)(s + OFF_W2 + (n8 * 8 + 2 * t4) * 4);
    float b2v = ((const float*)(s + OFF_B2))[0];

    // persist B fragments (Wh, Wl)
    uint32_t Bh[4][4][2], Bl[4][4][2];
#pragma unroll
    for (int n8 = 0; n8 < 4; n8++)
#pragma unroll
        for (int kg = 0; kg < 4; kg++) {
            uint32_t ba = sb + OFF_WH + (n8 * 8 + (l & 7)) * STRB
                        + ((l >> 3) & 1) * 16 + kg * 32;
            ldsm_x2(Bh[n8][kg], ba);
            ldsm_x2(Bl[n8][kg], ba + (OFF_WL - OFF_WH));
        }

#pragma unroll
    for (int si = 0; si < 2; si++) {
        int rowbase = w * 32 + si * 16;
        uint32_t aH = sb + OFF_AH + (rowbase + (l & 15)) * STRB + (l >> 4) * 16;
        uint32_t aL = aH + (OFF_AL - OFF_AH);

        float acc[4][4];
#pragma unroll
        for (int n8 = 0; n8 < 4; n8++)
#pragma unroll
            for (int c = 0; c < 4; c++) acc[n8][c] = 0.0f;

#pragma unroll
        for (int kg = 0; kg < 4; kg++) {
            uint32_t ah[4], al[4];
            ldsm_x4(ah, aH + kg * 32);
            ldsm_x4(al, aL + kg * 32);
#pragma unroll
            for (int n8 = 0; n8 < 4; n8++) {
                mma_bf16(acc[n8], ah, Bh[n8][kg]);
                mma_bf16(acc[n8], al, Bh[n8][kg]);
                mma_bf16(acc[n8], ah, Bl[n8][kg]);
            }
        }

        // ---- epilogue: rows g and g+8 of this subtile ----
        long giA = node0 + rowbase + g;
        long giB = giA + 8;
        bool vA = (giA < n), vB = (giB < n);
        int  segA = nb[vA ? giA : (n - 1)];
        int  segB = nb[vB ? giB : (n - 1)];

        float pA = 0.0f, pB = 0.0f;
#pragma unroll
        for (int n8 = 0; n8 < 4; n8++) {
            float2 ga = *(const float2*)(g_G + (size_t)segA * HID + n8 * 8 + 2 * t4);
            float2 gb = *(const float2*)(g_G + (size_t)segB * HID + n8 * 8 + 2 * t4);
            float a0 = acc[n8][0] + ga.x;
            float a1 = acc[n8][1] + ga.y;
            float a2 = acc[n8][2] + gb.x;
            float a3 = acc[n8][3] + gb.y;
            float s0 = (a0 > 20.0f) ? a0 : __logf(1.0f + __expf(a0));
            float s1 = (a1 > 20.0f) ? a1 : __logf(1.0f + __expf(a1));
            float s2 = (a2 > 20.0f) ? a2 : __logf(1.0f + __expf(a2));
            float s3 = (a3 > 20.0f) ? a3 : __logf(1.0f + __expf(a3));
            pA = fmaf(s0, w2p[n8].x, pA);
            pA = fmaf(s1, w2p[n8].y, pA);
            pB = fmaf(s2, w2p[n8].x, pB);
            pB = fmaf(s3, w2p[n8].y, pB);
        }
        pA += __shfl_xor_sync(0xFFFFFFFFu, pA, 1);
        pA += __shfl_xor_sync(0xFFFFFFFFu, pA, 2);
        pB += __shfl_xor_sync(0xFFFFFFFFu, pB, 1);
        pB += __shfl_xor_sync(0xFFFFFFFFu, pB, 2);
        float lgA = pA + b2v;
        float lgB = pB + b2v;

        if (t4 == 0) {
            if (vA) g_logit[giA] = lgA;
            if (vB) g_logit[giB] = lgB;
            if (vA && vB && segA == segB) {
                atomicMax(&g_maxenc[segA], enc_f(fmaxf(lgA, lgB)));
            } else {
                if (vA) atomicMax(&g_maxenc[segA], enc_f(lgA));
                if (vB) atomicMax(&g_maxenc[segB], enc_f(lgB));
            }
        }
    }
}

// ---------------------------------------------------------------------------
__global__ void __launch_bounds__(256)
k_exp(const int* __restrict__ nb, int n) {
    int i = blockIdx.x * blockDim.x + threadIdx.x;
    int lane = threadIdx.x & 31;

    int   seg = -1;
    float e   = 0.0f;
    if (i < n) {
        seg = nb[i];
        float mx = dec_f(g_maxenc[seg]);
        e = __expf(g_logit[i] - mx);
    }
#pragma unroll
    for (int off = 1; off < 32; off <<= 1) {
        int   os = __shfl_down_sync(0xFFFFFFFFu, seg, off);
        float oe = __shfl_down_sync(0xFFFFFFFFu, e,   off);
        if (lane + off < 32 && os == seg) e += oe;
    }
    int  ps   = __shfl_up_sync(0xFFFFFFFFu, seg, 1);
    bool head = (lane == 0) || (ps != seg);
    if (head && seg >= 0) atomicAdd(&g_sum[seg], e);
}

// ---------------------------------------------------------------------------
__global__ void __launch_bounds__(256)
k_div(const int* __restrict__ nb, float* __restrict__ out, int n) {
    int i = blockIdx.x * blockDim.x + threadIdx.x;
    if (i < n) {
        int   seg = nb[i];
        float mx  = dec_f(g_maxenc[seg]);
        float e   = __expf(g_logit[i] - mx);
        out[i] = e / g_sum[seg];
    }
}

// ---------------------------------------------------------------------------
extern "C" void kernel_launch(void* const* d_in, const int* in_sizes, int n_in,
                              void* d_out, int out_size) {
    const float* x   = (const float*)d_in[0];
    const int*   nb  = (const int*)d_in[1];
    const float* gf  = (const float*)d_in[2];
    const float* W1  = (const float*)d_in[3];
    const float* b1  = (const float*)d_in[4];
    const float* W2  = (const float*)d_in[5];
    const float* b2  = (const float*)d_in[6];
    float*       out = (float*)d_out;

    int n = in_sizes[0] / NEU;   // nodes
    int b = in_sizes[2] / GD;    // graphs

    k_init<<<(b + 255) / 256, 256>>>(b);
    k_graph<<<(b + 7) / 8, 256>>>(gf, W1, b1, b);

    int ntiles = (n + 127) / 128;
    k_logits<<<ntiles, 128>>>(x, nb, W1, W2, b2, n);

    int blocks = (n + 255) / 256;
    k_exp<<<blocks, 256>>>(nb, n);
    k_div<<<blocks, 256>>>(nb, out, n);
}

// round 10
// speedup vs baseline: 2.9557x; 1.3457x over previous
#include <cuda_runtime.h>
#include <cuda_bf16.h>
#include <cstdint>

#define NEU   64
#define HID   32
#define GD    103
#define N_MAX 2000128
#define B_MAX 8192

typedef unsigned long long ull;

// Scratch
__device__ float        g_logit[N_MAX];
__device__ float        g_G[B_MAX * HID];
__device__ unsigned int g_maxenc[B_MAX];
__device__ float        g_sum[B_MAX];

__device__ __forceinline__ unsigned int enc_f(float f) {
    unsigned int u = __float_as_uint(f);
    return (u & 0x80000000u) ? ~u : (u | 0x80000000u);
}
__device__ __forceinline__ float dec_f(unsigned int u) {
    u = (u & 0x80000000u) ? (u & 0x7FFFFFFFu) : ~u;
    return __uint_as_float(u);
}

__device__ __forceinline__ uint32_t smem_u32(const void* p) {
    uint32_t a;
    asm("{ .reg .u64 t; cvta.to.shared.u64 t, %1; cvt.u32.u64 %0, t; }"
        : "=r"(a) : "l"(p));
    return a;
}
__device__ __forceinline__ void ldsm_x4(uint32_t r[4], uint32_t addr) {
    asm volatile("ldmatrix.sync.aligned.m8n8.x4.shared.b16 {%0,%1,%2,%3}, [%4];"
        : "=r"(r[0]), "=r"(r[1]), "=r"(r[2]), "=r"(r[3]) : "r"(addr));
}
__device__ __forceinline__ void ldsm_x2(uint32_t r[2], uint32_t addr) {
    asm volatile("ldmatrix.sync.aligned.m8n8.x2.shared.b16 {%0,%1}, [%2];"
        : "=r"(r[0]), "=r"(r[1]) : "r"(addr));
}
__device__ __forceinline__ void mma_bf16(float c[4], const uint32_t a[4],
                                         const uint32_t b[2]) {
    asm volatile(
        "mma.sync.aligned.m16n8k16.row.col.f32.bf16.bf16.f32 "
        "{%0,%1,%2,%3}, {%4,%5,%6,%7}, {%8,%9}, {%0,%1,%2,%3};"
        : "+f"(c[0]), "+f"(c[1]), "+f"(c[2]), "+f"(c[3])
        : "r"(a[0]), "r"(a[1]), "r"(a[2]), "r"(a[3]), "r"(b[0]), "r"(b[1]));
}

// ---------------------------------------------------------------------------
__global__ void k_init(int b) {
    int i = blockIdx.x * blockDim.x + threadIdx.x;
    if (i < b) { g_maxenc[i] = 0u; g_sum[i] = 0.0f; }
}

// ---------------------------------------------------------------------------
__global__ void k_graph(const float* __restrict__ gf,
                        const float* __restrict__ W1,
                        const float* __restrict__ b1, int b) {
    int warp = (blockIdx.x * blockDim.x + threadIdx.x) >> 5;
    int lane = threadIdx.x & 31;
    if (warp >= b) return;

    const float* row = gf + (size_t)warp * GD;
    float r0 = row[lane];
    float r1 = row[32 + lane];
    float r2 = row[64 + lane];
    float r3 = (lane < (GD - 96)) ? row[96 + lane] : 0.0f;

    float acc = b1[lane];
#pragma unroll
    for (int d = 0; d < GD; d++) {
        float v;
        if      (d < 32) v = __shfl_sync(0xFFFFFFFFu, r0, d);
        else if (d < 64) v = __shfl_sync(0xFFFFFFFFu, r1, d - 32);
        else if (d < 96) v = __shfl_sync(0xFFFFFFFFu, r2, d - 64);
        else             v = __shfl_sync(0xFFFFFFFFu, r3, d - 96);
        acc = fmaf(v, W1[(NEU + d) * HID + lane], acc);
    }
    g_G[warp * HID + lane] = acc;
}

// ---------------------------------------------------------------------------
// k_logits v8: persistent warps + bf16-split HMMA.
//   Setup (W1 transpose/split, B fragments, W2, b2) once per CTA.
//   Each warp independently grid-strides over 32-node tiles with a private
//   hi/lo staging buffer; only __syncwarp in the steady state.
// ---------------------------------------------------------------------------
#define STRB   144                       // bytes per smem row (64 bf16 + pad)
#define WBUF   9216                      // per-warp: AH (4608) + AL (4608)
#define OFF_WH 36864                     // 4 warps * WBUF
#define OFF_WL 41472
#define OFF_W2 46080
#define OFF_B2 46208
#define SMEMSZ 46336

__global__ void __launch_bounds__(128)
k_logits(const float* __restrict__ x,
         const int* __restrict__ nb,
         const float* __restrict__ W1,
         const float* __restrict__ W2,
         const float* __restrict__ b2, int n) {
    __shared__ __align__(128) char s[SMEMSZ];
    uint32_t sb  = smem_u32(s);
    int tid = threadIdx.x;
    int w   = tid >> 5;
    int l   = tid & 31;

    // ---- once per CTA: W1[0:64] -> Wh/Wl [h][k] bf16 tiles ----
    for (int t = tid; t < NEU * HID; t += 128) {
        int k = t >> 5, h = t & 31;          // W1[k][h] = W1[t]
        float wv = W1[t];
        __nv_bfloat16 wh = __float2bfloat16(wv);
        float wl = wv - __bfloat162float(wh);
        ((__nv_bfloat16*)(s + OFF_WH))[h * 72 + k] = wh;
        ((__nv_bfloat16*)(s + OFF_WL))[h * 72 + k] = __float2bfloat16(wl);
    }
    if (tid < HID) ((float*)(s + OFF_W2))[tid] = W2[tid];
    if (tid == 0)  ((float*)(s + OFF_B2))[0]   = b2[0];
    __syncthreads();

    int g = l >> 2, t4 = l & 3;

    // once per warp: W2 pairs, b2, B fragments
    float2 w2p[4];
#pragma unroll
    for (int n8 = 0; n8 < 4; n8++)
        w2p[n8] = *(const float2*)(s + OFF_W2 + (n8 * 8 + 2 * t4) * 4);
    float b2v = ((const float*)(s + OFF_B2))[0];

    uint32_t Bh[4][4][2], Bl[4][4][2];
#pragma unroll
    for (int n8 = 0; n8 < 4; n8++)
#pragma unroll
        for (int kg = 0; kg < 4; kg++) {
            uint32_t ba = sb + OFF_WH + (n8 * 8 + (l & 7)) * STRB
                        + ((l >> 3) & 1) * 16 + kg * 32;
            ldsm_x2(Bh[n8][kg], ba);
            ldsm_x2(Bl[n8][kg], ba + (OFF_WL - OFF_WH));
        }

    uint32_t aBase = sb + w * WBUF;          // AH; AL at +4608
    int m = l & 15, half = l >> 4;

    long ntiles = (n + 31) / 32;
    long wstep  = (long)gridDim.x * 4;

    for (long tile = (long)blockIdx.x * 4 + w; tile < ntiles; tile += wstep) {
        long node0 = tile * 32;

        // ---- stage this warp's 32 nodes (coalesced LDG.128) ----
#pragma unroll
        for (int j = 0; j < 16; j++) {
            int  nl = 2 * j + half;
            long gn = node0 + nl;
            if (gn > n - 1) gn = n - 1;
            float4 v = *(const float4*)(x + gn * NEU + m * 4);
            __nv_bfloat162 h0 = __floats2bfloat162_rn(v.x, v.y);
            __nv_bfloat162 h1 = __floats2bfloat162_rn(v.z, v.w);
            __nv_bfloat162 l0 = __floats2bfloat162_rn(v.x - __bfloat162float(h0.x),
                                                      v.y - __bfloat162float(h0.y));
            __nv_bfloat162 l1 = __floats2bfloat162_rn(v.z - __bfloat162float(h1.x),
                                                      v.w - __bfloat162float(h1.y));
            union { __nv_bfloat162 p[2]; ull u; } ph, pl;
            ph.p[0] = h0; ph.p[1] = h1;
            pl.p[0] = l0; pl.p[1] = l1;
            *(ull*)(s + w * WBUF + nl * STRB + m * 8)        = ph.u;
            *(ull*)(s + w * WBUF + 4608 + nl * STRB + m * 8) = pl.u;
        }
        __syncwarp();

#pragma unroll
        for (int si = 0; si < 2; si++) {
            uint32_t aH = aBase + (si * 16 + (l & 15)) * STRB + (l >> 4) * 16;
            uint32_t aL = aH + 4608;

            float acc[4][4];
#pragma unroll
            for (int n8 = 0; n8 < 4; n8++)
#pragma unroll
                for (int c = 0; c < 4; c++) acc[n8][c] = 0.0f;

#pragma unroll
            for (int kg = 0; kg < 4; kg++) {
                uint32_t ah[4], al[4];
                ldsm_x4(ah, aH + kg * 32);
                ldsm_x4(al, aL + kg * 32);
#pragma unroll
                for (int n8 = 0; n8 < 4; n8++) {
                    mma_bf16(acc[n8], ah, Bh[n8][kg]);
                    mma_bf16(acc[n8], al, Bh[n8][kg]);
                    mma_bf16(acc[n8], ah, Bl[n8][kg]);
                }
            }

            // ---- epilogue: rows g and g+8 of this subtile ----
            long giA = node0 + si * 16 + g;
            long giB = giA + 8;
            bool vA = (giA < n), vB = (giB < n);
            int  segA = nb[vA ? giA : (n - 1)];
            int  segB = nb[vB ? giB : (n - 1)];

            float pA = 0.0f, pB = 0.0f;
#pragma unroll
            for (int n8 = 0; n8 < 4; n8++) {
                float2 ga = *(const float2*)(g_G + (size_t)segA * HID + n8 * 8 + 2 * t4);
                float2 gb = *(const float2*)(g_G + (size_t)segB * HID + n8 * 8 + 2 * t4);
                float a0 = acc[n8][0] + ga.x;
                float a1 = acc[n8][1] + ga.y;
                float a2 = acc[n8][2] + gb.x;
                float a3 = acc[n8][3] + gb.y;
                float s0 = (a0 > 20.0f) ? a0 : __logf(1.0f + __expf(a0));
                float s1 = (a1 > 20.0f) ? a1 : __logf(1.0f + __expf(a1));
                float s2 = (a2 > 20.0f) ? a2 : __logf(1.0f + __expf(a2));
                float s3 = (a3 > 20.0f) ? a3 : __logf(1.0f + __expf(a3));
                pA = fmaf(s0, w2p[n8].x, pA);
                pA = fmaf(s1, w2p[n8].y, pA);
                pB = fmaf(s2, w2p[n8].x, pB);
                pB = fmaf(s3, w2p[n8].y, pB);
            }
            pA += __shfl_xor_sync(0xFFFFFFFFu, pA, 1);
            pA += __shfl_xor_sync(0xFFFFFFFFu, pA, 2);
            pB += __shfl_xor_sync(0xFFFFFFFFu, pB, 1);
            pB += __shfl_xor_sync(0xFFFFFFFFu, pB, 2);
            float lgA = pA + b2v;
            float lgB = pB + b2v;

            if (t4 == 0) {
                if (vA) g_logit[giA] = lgA;
                if (vB) g_logit[giB] = lgB;
                if (vA && vB && segA == segB) {
                    atomicMax(&g_maxenc[segA], enc_f(fmaxf(lgA, lgB)));
                } else {
                    if (vA) atomicMax(&g_maxenc[segA], enc_f(lgA));
                    if (vB) atomicMax(&g_maxenc[segB], enc_f(lgB));
                }
            }
        }
        __syncwarp();
    }
}

// ---------------------------------------------------------------------------
__global__ void __launch_bounds__(256)
k_exp(const int* __restrict__ nb, int n) {
    int i = blockIdx.x * blockDim.x + threadIdx.x;
    int lane = threadIdx.x & 31;

    int   seg = -1;
    float e   = 0.0f;
    if (i < n) {
        seg = nb[i];
        float mx = dec_f(g_maxenc[seg]);
        e = __expf(g_logit[i] - mx);
    }
#pragma unroll
    for (int off = 1; off < 32; off <<= 1) {
        int   os = __shfl_down_sync(0xFFFFFFFFu, seg, off);
        float oe = __shfl_down_sync(0xFFFFFFFFu, e,   off);
        if (lane + off < 32 && os == seg) e += oe;
    }
    int  ps   = __shfl_up_sync(0xFFFFFFFFu, seg, 1);
    bool head = (lane == 0) || (ps != seg);
    if (head && seg >= 0) atomicAdd(&g_sum[seg], e);
}

// ---------------------------------------------------------------------------
__global__ void __launch_bounds__(256)
k_div(const int* __restrict__ nb, float* __restrict__ out, int n) {
    int i = blockIdx.x * blockDim.x + threadIdx.x;
    if (i < n) {
        int   seg = nb[i];
        float mx  = dec_f(g_maxenc[seg]);
        float e   = __expf(g_logit[i] - mx);
        out[i] = e / g_sum[seg];
    }
}

// ---------------------------------------------------------------------------
extern "C" void kernel_launch(void* const* d_in, const int* in_sizes, int n_in,
                              void* d_out, int out_size) {
    const float* x   = (const float*)d_in[0];
    const int*   nb  = (const int*)d_in[1];
    const float* gf  = (const float*)d_in[2];
    const float* W1  = (const float*)d_in[3];
    const float* b1  = (const float*)d_in[4];
    const float* W2  = (const float*)d_in[5];
    const float* b2  = (const float*)d_in[6];
    float*       out = (float*)d_out;

    int n = in_sizes[0] / NEU;   // nodes
    int b = in_sizes[2] / GD;    // graphs

    k_init<<<(b + 255) / 256, 256>>>(b);
    k_graph<<<(b + 7) / 8, 256>>>(gf, W1, b1, b);

    k_logits<<<592, 128>>>(x, nb, W1, W2, b2, n);

    int blocks = (n + 255) / 256;
    k_exp<<<blocks, 256>>>(nb, n);
    k_div<<<blocks, 256>>>(nb, out, n);
}